// round 8
// baseline (speedup 1.0000x reference)
#include <cuda_runtime.h>
#include <cuda_bf16.h>
#include <cstdint>
#include <math.h>

// Problem constants
#define Bb 4
#define Hh 4
#define Ss 2048
#define Dd 512
#define Uu 1024
#define BS 8192          // Bb*Ss
#define HU 4096          // Hh*Uu

// Arch feature gate: tcgen05 only exists on the 'a' variants.
#if defined(__CUDA_ARCH_FEAT_SM103_ALL) || defined(__CUDA_ARCH_FEAT_SM100_ALL)
#define HAS_TCGEN05 1
#else
#define HAS_TCGEN05 0
#endif

// ---------------------------------------------------------------------------
// Device scratch (no cudaMalloc allowed)
// ---------------------------------------------------------------------------
__device__ float g_xn[BS * Dd];                       // 16 MB
__device__ float g_q[(size_t)Hh * BS * Uu];           // 134 MB
__device__ float g_k[(size_t)Hh * BS * Uu];           // 134 MB
__device__ float g_v[(size_t)Hh * BS * Uu];           // 134 MB
__device__ float g_vt[(size_t)Hh * BS * Uu];          // 134 MB (V^T [h][b][u][t])
__device__ float g_sc[(size_t)Bb * Hh * Ss * Ss];     // 268 MB
__device__ float g_cat[(size_t)BS * HU];              // 134 MB
__device__ float g_wt[(size_t)3 * Hh * Uu * Dd];      // 25 MB  (W^T for q,k,v)
__device__ float g_wot[(size_t)Dd * HU];              // 8 MB   (Wout^T [512][4096])

// ---------------------------------------------------------------------------
// helpers
// ---------------------------------------------------------------------------
__device__ __forceinline__ uint32_t smem_u32(const void* p) {
    uint32_t a;
    asm("{ .reg .u64 t; cvta.to.shared.u64 t, %1; cvt.u32.u64 %0, t; }" : "=r"(a) : "l"(p));
    return a;
}
__device__ __forceinline__ uint32_t cluster_rank() {
    uint32_t r;
    asm("mov.u32 %0, %%cluster_ctarank;" : "=r"(r));
    return r;
}

#if HAS_TCGEN05
__device__ __forceinline__ uint32_t elect_one() {
    uint32_t pred;
    asm volatile("{\n\t.reg .pred p;\n\telect.sync _|p, 0xFFFFFFFF;\n\t"
                 "selp.b32 %0, 1, 0, p;\n\t}" : "=r"(pred));
    return pred;
}
#define MBAR_INIT(addr, cnt) \
    asm volatile("mbarrier.init.shared.b64 [%0], %1;" :: "r"(addr), "r"(cnt) : "memory")
#define MBAR_WAIT(addr, parity) do {                                              \
    uint32_t _m = (addr), _p = (parity), _d;                                      \
    asm volatile("{\n\t.reg .pred p;\n\t"                                         \
        "mbarrier.try_wait.parity.acquire.cta.shared::cta.b64 p, [%1], %2;\n\t"   \
        "selp.b32 %0, 1, 0, p;\n\t}" : "=r"(_d) : "r"(_m), "r"(_p) : "memory");   \
    if (!_d) {                                                                    \
        asm volatile("{\n\t.reg .pred P1;\n\t"                                    \
            "W_%=:\n\t"                                                           \
            "mbarrier.try_wait.parity.acquire.cta.shared::cta.b64 P1, [%0], %1, 0x989680;\n\t" \
            "@P1 bra.uni D_%=;\n\t"                                               \
            "bra.uni W_%=;\n\t"                                                   \
            "D_%=:\n\t}" :: "r"(_m), "r"(_p) : "memory");                         \
    }                                                                             \
} while (0)
#define TC_ALLOC_CG2(smem_addr, n) \
    asm volatile("tcgen05.alloc.cta_group::2.sync.aligned.shared::cta.b32 [%0], %1;" \
                 :: "r"(smem_addr), "r"((uint32_t)(n)) : "memory")
#define TC_DEALLOC_CG2(tmem, n) \
    asm volatile("tcgen05.dealloc.cta_group::2.sync.aligned.b32 %0, %1;" :: "r"(tmem), "r"((uint32_t)(n)))
#define TC_COMMIT_MC2(mbar) \
    asm volatile("tcgen05.commit.cta_group::2.mbarrier::arrive::one.shared::cluster.multicast::cluster.b64 [%0], %1;" \
                 :: "r"(mbar), "h"((uint16_t)3) : "memory")
#define TC_FENCE_AFTER()  asm volatile("tcgen05.fence::after_thread_sync;" ::: "memory")
#define TC_WAIT_LD()      asm volatile("tcgen05.wait::ld.sync.aligned;" ::: "memory")
#define FENCE_ASYNC()     asm volatile("fence.proxy.async.shared::cta;" ::: "memory")
#define CLUSTER_SYNC() do { \
    asm volatile("barrier.cluster.arrive.aligned;" ::: "memory"); \
    asm volatile("barrier.cluster.wait.aligned;" ::: "memory"); \
} while (0)

#define LDTM_X32(r, addr)                                                         \
    asm volatile("tcgen05.ld.sync.aligned.32x32b.x32.b32 "                        \
        "{%0, %1, %2, %3, %4, %5, %6, %7, %8, %9, %10, %11, %12, %13, %14, %15, " \
        " %16, %17, %18, %19, %20, %21, %22, %23, %24, %25, %26, %27, %28, %29, %30, %31}, [%32];" \
        : "=r"((r)[0]), "=r"((r)[1]), "=r"((r)[2]), "=r"((r)[3]),                 \
          "=r"((r)[4]), "=r"((r)[5]), "=r"((r)[6]), "=r"((r)[7]),                 \
          "=r"((r)[8]), "=r"((r)[9]), "=r"((r)[10]), "=r"((r)[11]),               \
          "=r"((r)[12]), "=r"((r)[13]), "=r"((r)[14]), "=r"((r)[15]),             \
          "=r"((r)[16]), "=r"((r)[17]), "=r"((r)[18]), "=r"((r)[19]),             \
          "=r"((r)[20]), "=r"((r)[21]), "=r"((r)[22]), "=r"((r)[23]),             \
          "=r"((r)[24]), "=r"((r)[25]), "=r"((r)[26]), "=r"((r)[27]),             \
          "=r"((r)[28]), "=r"((r)[29]), "=r"((r)[30]), "=r"((r)[31])              \
        : "r"(addr))

__device__ __forceinline__ void sts64(uint32_t addr, uint32_t a, uint32_t b) {
    asm volatile("st.shared.v2.b32 [%0], {%1,%2};"
                 :: "r"(addr), "r"(a), "r"(b) : "memory");
}

// pack two f32 into bf16x2 (low = x) with a single cvt
__device__ __forceinline__ uint32_t packbf2(float x, float y) {
    uint32_t r;
    asm("cvt.rn.bf16x2.f32 %0, %1, %2;" : "=r"(r) : "f"(y), "f"(x));
    return r;
}

// SMEM descriptor, SW128, LBO=1 (16B), SBO=64 (1024B)
__device__ __forceinline__ uint64_t make_desc(uint32_t addr) {
    const uint64_t base = (2ULL << 61) | (1ULL << 46) | (64ULL << 32) | (1ULL << 16);
    return base | (uint64_t)((addr >> 4) & 0x3FFF);
}
// cg2 f16(bf16) SS MMA: M=256 across the pair
__device__ __forceinline__ void mma_cg2(uint32_t d, uint64_t ad, uint64_t bd,
                                        uint32_t idesc, uint32_t en) {
    asm volatile("{\n\t.reg .pred p;\n\tsetp.ne.u32 p, %4, 0;\n\t"
        "tcgen05.mma.cta_group::2.kind::f16 [%0], %1, %2, %3, "
        "{%5,%5,%5,%5,%5,%5,%5,%5}, p;\n\t}"
        :: "r"(d), "l"(ad), "l"(bd), "r"(idesc), "r"(en), "r"(0u) : "memory");
}
#endif  // HAS_TCGEN05

// idesc: fp32 accum, bf16 A/B, M=256 (cg2), N=128
//   (256/16)<<24 | (128/8)<<17 | dtype F32 | atype BF16 | btype BF16
#define IDESC_CG2 0x10200490u

// SMEM per CTA: A half 128x64 hi/lo + two B panels 64x64 hi/lo
#define SM_AHI  0
#define SM_ALO  16384
#define SM_B0HI 32768
#define SM_B0LO 40960
#define SM_B1HI 49152
#define SM_B1LO 57344
#define SM_MBDN 65536
#define SM_TPTR 65544
#define SMEM_BYTES 65568

#if HAS_TCGEN05
// ---------------------------------------------------------------------------
// Two-phase stage (round-7 proven): fp32 K-major tile -> hi/lo bf16 SW128.
// 16 threads/row contiguous LDG.128; rows staged = ITERS * 16.
// ---------------------------------------------------------------------------
template <int ITERS>
__device__ __forceinline__ void stage(const float* __restrict__ src, int ld,
                                      uint32_t hi, uint32_t lo, int tid) {
    float4 v[ITERS];
#pragma unroll
    for (int i = 0; i < ITERS; i++) {
        int idx = tid + i * 256;
        int r = idx >> 4, q = idx & 15;
        v[i] = *(const float4*)(src + (size_t)r * ld + (q << 2));
    }
#pragma unroll
    for (int i = 0; i < ITERS; i++) {
        int idx = tid + i * 256;
        int r = idx >> 4, q = idx & 15;
        uint32_t h0 = packbf2(v[i].x, v[i].y);
        uint32_t h1 = packbf2(v[i].z, v[i].w);
        uint32_t l0 = packbf2(v[i].x - __uint_as_float(h0 << 16),
                              v[i].y - __uint_as_float(h0 & 0xFFFF0000u));
        uint32_t l1 = packbf2(v[i].z - __uint_as_float(h1 << 16),
                              v[i].w - __uint_as_float(h1 & 0xFFFF0000u));
        uint32_t b0 = (uint32_t)(r * 128 + (q << 3));
        uint32_t o = b0 ^ ((b0 >> 3) & 0x70);
        sts64(hi + o, h0, h1);
        sts64(lo + o, l0, l1);
    }
}
#endif

// ---------------------------------------------------------------------------
// Main GEMM (cg2 cluster pair): C[256 x 256] = A[256 x kmax] * B[256 x kmax]^T
// Rank r stages A rows [r*128,+128) and B rows [p*128+r*64,+64) per panel p.
// fp32 K-major operands, bf16-split 3-pass emulation. kmax multiple of 64.
// ---------------------------------------------------------------------------
__device__ void gemm_main(const float* __restrict__ A, int lda,
                          const float* __restrict__ B, int ldb,
                          float* __restrict__ C, int ldc, int kmax) {
    uint32_t rank = cluster_rank();
    C += (size_t)(rank * 128) * ldc;           // this CTA's M half
#if HAS_TCGEN05
    extern __shared__ char smem[];
    uint32_t sb = smem_u32(smem);
    int tid = threadIdx.x;
    int wid = tid >> 5;
    int lane = tid & 31;

    if (wid == 0) TC_ALLOC_CG2(sb + SM_TPTR, 256);
    if (tid == 0) MBAR_INIT(sb + SM_MBDN, 1);
    __syncthreads();
    uint32_t tmem = *(volatile uint32_t*)(smem + SM_TPTR);
    CLUSTER_SYNC();   // mbars + alloc visible cluster-wide

    int nch = kmax >> 6;

    for (int c = 0; c < nch; c++) {
        if (c > 0) MBAR_WAIT(sb + SM_MBDN, (c - 1) & 1);
        stage<8>(A + (size_t)(rank * 128) * lda + c * 64, lda,
                 sb + SM_AHI, sb + SM_ALO, tid);
        stage<4>(B + (size_t)(rank * 64) * ldb + c * 64, ldb,
                 sb + SM_B0HI, sb + SM_B0LO, tid);
        stage<4>(B + (size_t)(128 + rank * 64) * ldb + c * 64, ldb,
                 sb + SM_B1HI, sb + SM_B1LO, tid);
        FENCE_ASYNC();
        CLUSTER_SYNC();   // both CTAs' tiles ready before pair-MMA
        if (rank == 0 && wid == 0) {
            if (elect_one()) {
                uint64_t ahi = make_desc(sb + SM_AHI);
                uint64_t alo = make_desc(sb + SM_ALO);
                uint64_t bh[2] = {make_desc(sb + SM_B0HI), make_desc(sb + SM_B1HI)};
                uint64_t bl[2] = {make_desc(sb + SM_B0LO), make_desc(sb + SM_B1LO)};
#pragma unroll
                for (int p = 0; p < 2; p++) {
                    uint64_t ap[3] = {ahi, ahi, alo};
                    uint64_t bp[3] = {bh[p], bl[p], bh[p]};
                    uint32_t d = tmem + (p << 7);
#pragma unroll
                    for (int pp = 0; pp < 3; pp++) {
#pragma unroll
                        for (int ks = 0; ks < 4; ks++) {
                            uint32_t en = !(c == 0 && pp == 0 && ks == 0);
                            mma_cg2(d, ap[pp] + ks * 2, bp[pp] + ks * 2,
                                    IDESC_CG2, en);
                        }
                    }
                }
                TC_COMMIT_MC2(sb + SM_MBDN);
            }
        }
    }

    MBAR_WAIT(sb + SM_MBDN, (nch - 1) & 1);
    TC_FENCE_AFTER();
    __syncthreads();

    // Epilogue: this CTA's D = 128 rows x 256 cols (2 panels x 128).
    // Warps 0-3 read panel 0, warps 4-7 panel 1, in parallel.
    int pw = wid >> 2, ws = wid & 3;
    float* sbuf = (float*)smem;   // 128 x 65 floats (33 KB, stage area reuse)
#pragma unroll
    for (int bt = 0; bt < 4; bt++) {
        uint32_t r[32];
        LDTM_X32(r, tmem + (pw << 7) + bt * 32);
        TC_WAIT_LD();
        int row = ws * 32 + lane;
#pragma unroll
        for (int j = 0; j < 32; j++)
            sbuf[row * 65 + pw * 32 + j] = __uint_as_float(r[j]);
        __syncthreads();
#pragma unroll
        for (int i = 0; i < 8; i++) {
            int idx = tid + i * 256;
            int rw = idx >> 4, c4 = (idx & 15) << 2;
            int gcol = ((c4 >= 32) ? 128 : 0) + bt * 32 + (c4 & 31);
            float4 v = make_float4(sbuf[rw * 65 + c4], sbuf[rw * 65 + c4 + 1],
                                   sbuf[rw * 65 + c4 + 2], sbuf[rw * 65 + c4 + 3]);
            *(float4*)(C + (size_t)rw * ldc + gcol) = v;
        }
        __syncthreads();
    }
    if (wid == 0) TC_DEALLOC_CG2(tmem, 256);
    CLUSTER_SYNC();   // no CTA exits while peer MMA/TMEM traffic in flight

#else  // ----- fp32 SIMT fallback (plain sm_103 PTX pass; never selected) -----
    int tid = threadIdx.x;
    for (int e = tid; e < 128 * 256; e += 256) {
        int i = e >> 8, j = e & 255;
        float acc = 0.0f;
        for (int k = 0; k < kmax; k++)
            acc = fmaf(A[(size_t)(rank * 128 + i) * lda + k],
                       B[(size_t)j * ldb + k], acc);
        C[(size_t)i * ldc + j] = acc;
    }
#endif
}

// ---------------------------------------------------------------------------
// Block reduction (256 threads)
// ---------------------------------------------------------------------------
__device__ __forceinline__ float block_reduce(float v, bool is_max) {
    __shared__ float red[8];
    int lane = threadIdx.x & 31, w = threadIdx.x >> 5;
#pragma unroll
    for (int o = 16; o; o >>= 1) {
        float u = __shfl_xor_sync(0xffffffffu, v, o);
        v = is_max ? fmaxf(v, u) : (v + u);
    }
    if (lane == 0) red[w] = v;
    __syncthreads();
    if (w == 0) {
        float t = (lane < 8) ? red[lane] : (is_max ? -3.4e38f : 0.0f);
#pragma unroll
        for (int o = 4; o; o >>= 1) {
            float u = __shfl_xor_sync(0xffffffffu, t, o);
            t = is_max ? fmaxf(t, u) : (t + u);
        }
        if (lane == 0) red[0] = t;
    }
    __syncthreads();
    float r = red[0];
    __syncthreads();
    return r;
}

// ---------------------------------------------------------------------------
// LayerNorm
// ---------------------------------------------------------------------------
__global__ void ln_kernel(const float* __restrict__ x,
                          const float* __restrict__ gamma,
                          const float* __restrict__ beta) {
    int row = blockIdx.x;
    const float* xr = x + (size_t)row * Dd;
    float* o = g_xn + (size_t)row * Dd;
    int t = threadIdx.x;
    float v0 = xr[t], v1 = xr[t + 256];
    float mu = block_reduce(v0 + v1, false) * (1.0f / Dd);
    float d0 = v0 - mu, d1 = v1 - mu;
    float var = block_reduce(d0 * d0 + d1 * d1, false) * (1.0f / Dd);
    float inv = 1.0f / sqrtf(var + 1e-6f);
    o[t]       = d0 * inv * gamma[t]       + beta[t];
    o[t + 256] = d1 * inv * gamma[t + 256] + beta[t + 256];
}

// ---------------------------------------------------------------------------
// Tiled fp32 transpose: [R][C] -> [C][R], batched over blockIdx.z
// ---------------------------------------------------------------------------
__device__ __forceinline__ void tr_dev(const float* __restrict__ src,
                                       float* __restrict__ dst, int R, int C) {
    __shared__ float t[32][33];
    size_t bo = (size_t)blockIdx.z * R * C;
    int c0 = blockIdx.x * 32, r0 = blockIdx.y * 32;
    int tx = threadIdx.x, ty = threadIdx.y;
#pragma unroll
    for (int i = 0; i < 4; i++)
        t[ty + i * 8][tx] = src[bo + (size_t)(r0 + ty + i * 8) * C + c0 + tx];
    __syncthreads();
#pragma unroll
    for (int i = 0; i < 4; i++)
        dst[bo + (size_t)(c0 + ty + i * 8) * R + r0 + tx] = t[tx][ty + i * 8];
}

__global__ void trw_kernel(const float* __restrict__ src, int wsel) {
    tr_dev(src, g_wt + (size_t)wsel * Hh * Uu * Dd, Dd, Uu);
}
__global__ void trwo_kernel(const float* __restrict__ src) {
    tr_dev(src, g_wot, HU, Dd);
}
__global__ void trv_kernel() {
    tr_dev(g_v, g_vt, Ss, Uu);
}

// ---------------------------------------------------------------------------
// GEMM wrappers: cluster (2,1,1); tile col = blockIdx.x>>1 (256 wide)
// ---------------------------------------------------------------------------
__global__ __launch_bounds__(256, 2) __cluster_dims__(2, 1, 1) void qkv_tc() {
    int z = blockIdx.z;
    int which = z >> 2, h = z & 3;
    const float* Bp = g_wt + (size_t)z * Uu * Dd;
    float* Cb = (which == 0 ? g_q : which == 1 ? g_k : g_v) + (size_t)h * BS * Uu;
    int br = blockIdx.y * 256, bc = (blockIdx.x >> 1) * 256;
    gemm_main(g_xn + (size_t)br * Dd, Dd, Bp + (size_t)bc * Dd, Dd,
              Cb + (size_t)br * Uu + bc, Uu, Dd);
}

__global__ __launch_bounds__(256, 2) __cluster_dims__(2, 1, 1) void scores_tc() {
    int brT = blockIdx.y, bcT = blockIdx.x >> 1;
    if (bcT > brT) return;   // tile fully above causal diagonal
    int br = brT * 256, bc = bcT * 256;
    int z = blockIdx.z, b = z >> 2, h = z & 3;
    const float* Qh = g_q + ((size_t)h * BS + (size_t)b * Ss) * Uu;
    const float* Kh = g_k + ((size_t)h * BS + (size_t)b * Ss) * Uu;
    float* C = g_sc + (size_t)(b * Hh + h) * Ss * Ss;
    gemm_main(Qh + (size_t)br * Uu, Uu, Kh + (size_t)bc * Uu, Uu,
              C + (size_t)br * Ss + bc, Ss, Uu);
}

__global__ __launch_bounds__(256, 2) __cluster_dims__(2, 1, 1) void pv_tc() {
    int z = blockIdx.z, b = z >> 2, h = z & 3;
    int br = blockIdx.y * 256, bc = (blockIdx.x >> 1) * 256;
    const float* P = g_sc + (size_t)(b * Hh + h) * Ss * Ss;
    const float* Vt = g_vt + (size_t)(h * Bb + b) * Uu * Ss;
    float* C = g_cat + (size_t)(b * Ss + br) * HU + h * Uu + bc;
    gemm_main(P + (size_t)br * Ss, Ss, Vt + (size_t)bc * Ss, Ss, C, HU, br + 256);
}

__global__ __launch_bounds__(256, 2) __cluster_dims__(2, 1, 1) void out_tc(float* __restrict__ out) {
    int br = blockIdx.y * 256, bc = (blockIdx.x >> 1) * 256;
    gemm_main(g_cat + (size_t)br * HU, HU, g_wot + (size_t)bc * HU, HU,
              out + (size_t)br * Dd + bc, Dd, HU);
}

// ---------------------------------------------------------------------------
// Softmax (causal, unscaled). Zero-fills (i, 256-block end) for PV.
// ---------------------------------------------------------------------------
__global__ void softmax_kernel() {
    int row = blockIdx.x;
    int i = row & (Ss - 1);
    float* r = g_sc + (size_t)row * Ss;
    int n = i + 1;
    int t = threadIdx.x;

    float v[8];
    float m = -3.4e38f;
#pragma unroll
    for (int c = 0; c < 8; c++) {
        int j = t + c * 256;
        v[c] = (j < n) ? r[j] : -3.4e38f;
        m = fmaxf(m, v[c]);
    }
    m = block_reduce(m, true);
    float s = 0.0f;
#pragma unroll
    for (int c = 0; c < 8; c++) {
        v[c] = expf(v[c] - m);
        s += v[c];
    }
    s = block_reduce(s, false);
    float inv = 1.0f / s;
#pragma unroll
    for (int c = 0; c < 8; c++) {
        int j = t + c * 256;
        if (j < n) r[j] = v[c] * inv;
    }
    int end = ((i >> 8) + 1) << 8;   // 256-aligned (PV tile k-extent)
    for (int j = n + t; j < end; j += 256) r[j] = 0.0f;
}

// ---------------------------------------------------------------------------
extern "C" void kernel_launch(void* const* d_in, const int* in_sizes, int n_in,
                              void* d_out, int out_size) {
    const float* x     = (const float*)d_in[0];
    const float* gamma = (const float*)d_in[1];
    const float* beta  = (const float*)d_in[2];
    const float* Wq    = (const float*)d_in[3];
    const float* Wk    = (const float*)d_in[4];
    const float* Wv    = (const float*)d_in[5];
    const float* Wout  = (const float*)d_in[6];
    float* out = (float*)d_out;

    cudaFuncSetAttribute(qkv_tc,    cudaFuncAttributeMaxDynamicSharedMemorySize, SMEM_BYTES);
    cudaFuncSetAttribute(scores_tc, cudaFuncAttributeMaxDynamicSharedMemorySize, SMEM_BYTES);
    cudaFuncSetAttribute(pv_tc,     cudaFuncAttributeMaxDynamicSharedMemorySize, SMEM_BYTES);
    cudaFuncSetAttribute(out_tc,    cudaFuncAttributeMaxDynamicSharedMemorySize, SMEM_BYTES);

    dim3 tb(32, 8);

    ln_kernel<<<BS, 256>>>(x, gamma, beta);
    trw_kernel<<<dim3(Uu / 32, Dd / 32, Hh), tb>>>(Wq, 0);
    trw_kernel<<<dim3(Uu / 32, Dd / 32, Hh), tb>>>(Wk, 1);
    trw_kernel<<<dim3(Uu / 32, Dd / 32, Hh), tb>>>(Wv, 2);
    trwo_kernel<<<dim3(Dd / 32, HU / 32, 1), tb>>>(Wout);

    qkv_tc<<<dim3((Uu / 256) * 2, BS / 256, 12), 256, SMEM_BYTES>>>();
    trv_kernel<<<dim3(Uu / 32, Ss / 32, Bb * Hh), tb>>>();
    scores_tc<<<dim3((Ss / 256) * 2, Ss / 256, Bb * Hh), 256, SMEM_BYTES>>>();
    softmax_kernel<<<Bb * Hh * Ss, 256>>>();
    pv_tc<<<dim3((Uu / 256) * 2, Ss / 256, Bb * Hh), 256, SMEM_BYTES>>>();
    out_tc<<<dim3((Dd / 256) * 2, BS / 256), 256, SMEM_BYTES>>>(out);
}

// round 11
// speedup vs baseline: 1.1203x; 1.1203x over previous
#include <cuda_runtime.h>
#include <cuda_bf16.h>
#include <cstdint>
#include <math.h>

// Problem constants
#define Bb 4
#define Hh 4
#define Ss 2048
#define Dd 512
#define Uu 1024
#define BS 8192          // Bb*Ss
#define HU 4096          // Hh*Uu

// Arch feature gate: tcgen05 only exists on the 'a' variants.
#if defined(__CUDA_ARCH_FEAT_SM103_ALL) || defined(__CUDA_ARCH_FEAT_SM100_ALL)
#define HAS_TCGEN05 1
#else
#define HAS_TCGEN05 0
#endif

// ---------------------------------------------------------------------------
// Device scratch (no cudaMalloc allowed)
// ---------------------------------------------------------------------------
__device__ float g_xn[BS * Dd];                       // 16 MB
__device__ float g_q[(size_t)Hh * BS * Uu];           // 134 MB
__device__ float g_k[(size_t)Hh * BS * Uu];           // 134 MB
__device__ float g_v[(size_t)Hh * BS * Uu];           // 134 MB
__device__ float g_vt[(size_t)Hh * BS * Uu];          // 134 MB (V^T [h][b][u][t])
__device__ float g_sc[(size_t)Bb * Hh * Ss * Ss];     // 268 MB
__device__ float g_cat[(size_t)BS * HU];              // 134 MB
__device__ float g_wt[(size_t)3 * Hh * Uu * Dd];      // 25 MB  (W^T for q,k,v)
__device__ float g_wot[(size_t)Dd * HU];              // 8 MB   (Wout^T [512][4096])

// ---------------------------------------------------------------------------
// helpers
// ---------------------------------------------------------------------------
__device__ __forceinline__ uint32_t smem_u32(const void* p) {
    uint32_t a;
    asm("{ .reg .u64 t; cvta.to.shared.u64 t, %1; cvt.u32.u64 %0, t; }" : "=r"(a) : "l"(p));
    return a;
}
__device__ __forceinline__ uint32_t cluster_rank() {
    uint32_t r;
    asm("mov.u32 %0, %%cluster_ctarank;" : "=r"(r));
    return r;
}

#if HAS_TCGEN05
__device__ __forceinline__ uint32_t elect_one() {
    uint32_t pred;
    asm volatile("{\n\t.reg .pred p;\n\telect.sync _|p, 0xFFFFFFFF;\n\t"
                 "selp.b32 %0, 1, 0, p;\n\t}" : "=r"(pred));
    return pred;
}
#define MBAR_INIT(addr, cnt) \
    asm volatile("mbarrier.init.shared.b64 [%0], %1;" :: "r"(addr), "r"(cnt) : "memory")
#define MBAR_WAIT(addr, parity) do {                                              \
    uint32_t _m = (addr), _p = (parity), _d;                                      \
    asm volatile("{\n\t.reg .pred p;\n\t"                                         \
        "mbarrier.try_wait.parity.acquire.cta.shared::cta.b64 p, [%1], %2;\n\t"   \
        "selp.b32 %0, 1, 0, p;\n\t}" : "=r"(_d) : "r"(_m), "r"(_p) : "memory");   \
    if (!_d) {                                                                    \
        asm volatile("{\n\t.reg .pred P1;\n\t"                                    \
            "W_%=:\n\t"                                                           \
            "mbarrier.try_wait.parity.acquire.cta.shared::cta.b64 P1, [%0], %1, 0x989680;\n\t" \
            "@P1 bra.uni D_%=;\n\t"                                               \
            "bra.uni W_%=;\n\t"                                                   \
            "D_%=:\n\t}" :: "r"(_m), "r"(_p) : "memory");                         \
    }                                                                             \
} while (0)
// cluster-scope acquire wait (pairs with peer CTA's cluster arrive)
#define MBAR_WAIT_CLU(addr, parity) do {                                          \
    uint32_t _m = (addr), _p = (parity), _d;                                      \
    asm volatile("{\n\t.reg .pred p;\n\t"                                         \
        "mbarrier.try_wait.parity.acquire.cluster.shared::cta.b64 p, [%1], %2;\n\t" \
        "selp.b32 %0, 1, 0, p;\n\t}" : "=r"(_d) : "r"(_m), "r"(_p) : "memory");   \
    if (!_d) {                                                                    \
        asm volatile("{\n\t.reg .pred P1;\n\t"                                    \
            "W_%=:\n\t"                                                           \
            "mbarrier.try_wait.parity.acquire.cluster.shared::cta.b64 P1, [%0], %1, 0x989680;\n\t" \
            "@P1 bra.uni D_%=;\n\t"                                               \
            "bra.uni W_%=;\n\t"                                                   \
            "D_%=:\n\t}" :: "r"(_m), "r"(_p) : "memory");                         \
    }                                                                             \
} while (0)
// arrive at rank0's copy of the given smem mbar (ptx_helpers-proven form)
#define MBAR_ARRIVE_RANK0(addr) \
    asm volatile("{\n\t.reg .b32 ra;\n\t" \
        "mapa.shared::cluster.u32 ra, %0, 0;\n\t" \
        "mbarrier.arrive.shared::cluster.b64 _, [ra];\n\t}" \
        :: "r"(addr) : "memory")
#define TC_ALLOC_CG2(smem_addr, n) \
    asm volatile("tcgen05.alloc.cta_group::2.sync.aligned.shared::cta.b32 [%0], %1;" \
                 :: "r"(smem_addr), "r"((uint32_t)(n)) : "memory")
#define TC_DEALLOC_CG2(tmem, n) \
    asm volatile("tcgen05.dealloc.cta_group::2.sync.aligned.b32 %0, %1;" :: "r"(tmem), "r"((uint32_t)(n)))
#define TC_COMMIT_MC2(mbar) \
    asm volatile("tcgen05.commit.cta_group::2.mbarrier::arrive::one.shared::cluster.multicast::cluster.b64 [%0], %1;" \
                 :: "r"(mbar), "h"((uint16_t)3) : "memory")
#define TC_FENCE_AFTER()  asm volatile("tcgen05.fence::after_thread_sync;" ::: "memory")
#define TC_WAIT_LD()      asm volatile("tcgen05.wait::ld.sync.aligned;" ::: "memory")
#define FENCE_ASYNC()     asm volatile("fence.proxy.async.shared::cta;" ::: "memory")
#define CLUSTER_SYNC() do { \
    asm volatile("barrier.cluster.arrive.aligned;" ::: "memory"); \
    asm volatile("barrier.cluster.wait.aligned;" ::: "memory"); \
} while (0)

#define LDTM_X32(r, addr)                                                         \
    asm volatile("tcgen05.ld.sync.aligned.32x32b.x32.b32 "                        \
        "{%0, %1, %2, %3, %4, %5, %6, %7, %8, %9, %10, %11, %12, %13, %14, %15, " \
        " %16, %17, %18, %19, %20, %21, %22, %23, %24, %25, %26, %27, %28, %29, %30, %31}, [%32];" \
        : "=r"((r)[0]), "=r"((r)[1]), "=r"((r)[2]), "=r"((r)[3]),                 \
          "=r"((r)[4]), "=r"((r)[5]), "=r"((r)[6]), "=r"((r)[7]),                 \
          "=r"((r)[8]), "=r"((r)[9]), "=r"((r)[10]), "=r"((r)[11]),               \
          "=r"((r)[12]), "=r"((r)[13]), "=r"((r)[14]), "=r"((r)[15]),             \
          "=r"((r)[16]), "=r"((r)[17]), "=r"((r)[18]), "=r"((r)[19]),             \
          "=r"((r)[20]), "=r"((r)[21]), "=r"((r)[22]), "=r"((r)[23]),             \
          "=r"((r)[24]), "=r"((r)[25]), "=r"((r)[26]), "=r"((r)[27]),             \
          "=r"((r)[28]), "=r"((r)[29]), "=r"((r)[30]), "=r"((r)[31])              \
        : "r"(addr))

__device__ __forceinline__ void sts64(uint32_t addr, uint32_t a, uint32_t b) {
    asm volatile("st.shared.v2.b32 [%0], {%1,%2};"
                 :: "r"(addr), "r"(a), "r"(b) : "memory");
}

// pack two f32 into bf16x2 (low = x) with a single cvt
__device__ __forceinline__ uint32_t packbf2(float x, float y) {
    uint32_t r;
    asm("cvt.rn.bf16x2.f32 %0, %1, %2;" : "=r"(r) : "f"(y), "f"(x));
    return r;
}

// SMEM descriptor, SW128, LBO=1 (16B), SBO=64 (1024B)
__device__ __forceinline__ uint64_t make_desc(uint32_t addr) {
    const uint64_t base = (2ULL << 61) | (1ULL << 46) | (64ULL << 32) | (1ULL << 16);
    return base | (uint64_t)((addr >> 4) & 0x3FFF);
}
// cg2 f16(bf16) SS MMA: M=256 across the pair
__device__ __forceinline__ void mma_cg2(uint32_t d, uint64_t ad, uint64_t bd,
                                        uint32_t idesc, uint32_t en) {
    asm volatile("{\n\t.reg .pred p;\n\tsetp.ne.u32 p, %4, 0;\n\t"
        "tcgen05.mma.cta_group::2.kind::f16 [%0], %1, %2, %3, "
        "{%5,%5,%5,%5,%5,%5,%5,%5}, p;\n\t}"
        :: "r"(d), "l"(ad), "l"(bd), "r"(idesc), "r"(en), "r"(0u) : "memory");
}
#endif  // HAS_TCGEN05

// idesc: fp32 accum, bf16 A/B, M=256 (cg2), N=128 (round-8 proven)
#define IDESC_CG2 0x10200490u

// SMEM per CTA: A half 128x64 hi/lo + two B panels 64x64 hi/lo
#define SM_AHI  0
#define SM_ALO  16384
#define SM_B0HI 32768
#define SM_B0LO 40960
#define SM_B1HI 49152
#define SM_B1LO 57344
#define SM_MBDN 65536
#define SM_MBRDY 65544
#define SM_TPTR 65552
#define SMEM_BYTES 65576

#if HAS_TCGEN05
// ---------------------------------------------------------------------------
// Two-phase stage (round-7/8 proven): fp32 K-major tile -> hi/lo bf16 SW128.
// 16 threads/row contiguous LDG.128; rows staged = ITERS * 16.
// ---------------------------------------------------------------------------
template <int ITERS>
__device__ __forceinline__ void stage(const float* __restrict__ src, int ld,
                                      uint32_t hi, uint32_t lo, int tid) {
    float4 v[ITERS];
#pragma unroll
    for (int i = 0; i < ITERS; i++) {
        int idx = tid + i * 256;
        int r = idx >> 4, q = idx & 15;
        v[i] = *(const float4*)(src + (size_t)r * ld + (q << 2));
    }
#pragma unroll
    for (int i = 0; i < ITERS; i++) {
        int idx = tid + i * 256;
        int r = idx >> 4, q = idx & 15;
        uint32_t h0 = packbf2(v[i].x, v[i].y);
        uint32_t h1 = packbf2(v[i].z, v[i].w);
        uint32_t l0 = packbf2(v[i].x - __uint_as_float(h0 << 16),
                              v[i].y - __uint_as_float(h0 & 0xFFFF0000u));
        uint32_t l1 = packbf2(v[i].z - __uint_as_float(h1 << 16),
                              v[i].w - __uint_as_float(h1 & 0xFFFF0000u));
        uint32_t b0 = (uint32_t)(r * 128 + (q << 3));
        uint32_t o = b0 ^ ((b0 >> 3) & 0x70);
        sts64(hi + o, h0, h1);
        sts64(lo + o, l0, l1);
    }
}
#endif

// ---------------------------------------------------------------------------
// Main GEMM (cg2 cluster pair): C[256 x 256] = A[256 x kmax] * B[256 x kmax]^T
// Rank r stages A rows [r*128,+128) and B rows [p*128+r*64,+64) per panel p.
// Per-chunk sync: mbarrier ready (2 arrivals -> rank0) + multicast done.
// fp32 K-major operands, bf16-split 3-pass emulation. kmax multiple of 64.
// ---------------------------------------------------------------------------
__device__ void gemm_main(const float* __restrict__ A, int lda,
                          const float* __restrict__ B, int ldb,
                          float* __restrict__ C, int ldc, int kmax) {
    uint32_t rank = cluster_rank();
    C += (size_t)(rank * 128) * ldc;           // this CTA's M half
#if HAS_TCGEN05
    extern __shared__ char smem[];
    uint32_t sb = smem_u32(smem);
    int tid = threadIdx.x;
    int wid = tid >> 5;
    int lane = tid & 31;

    if (wid == 0) TC_ALLOC_CG2(sb + SM_TPTR, 256);
    if (tid == 0) {
        MBAR_INIT(sb + SM_MBDN, 1);
        MBAR_INIT(sb + SM_MBRDY, 2);
    }
    __syncthreads();
    uint32_t tmem = *(volatile uint32_t*)(smem + SM_TPTR);
    CLUSTER_SYNC();   // mbars + alloc visible cluster-wide

    int nch = kmax >> 6;

    for (int c = 0; c < nch; c++) {
        if (c > 0) MBAR_WAIT(sb + SM_MBDN, (c - 1) & 1);
        stage<8>(A + (size_t)(rank * 128) * lda + c * 64, lda,
                 sb + SM_AHI, sb + SM_ALO, tid);
        stage<4>(B + (size_t)(rank * 64) * ldb + c * 64, ldb,
                 sb + SM_B0HI, sb + SM_B0LO, tid);
        stage<4>(B + (size_t)(128 + rank * 64) * ldb + c * 64, ldb,
                 sb + SM_B1HI, sb + SM_B1LO, tid);
        FENCE_ASYNC();
        __syncthreads();
        if (tid == 0) MBAR_ARRIVE_RANK0(sb + SM_MBRDY);   // both ranks -> rank0
        if (rank == 0 && wid == 0) {
            if (elect_one()) {
                MBAR_WAIT_CLU(sb + SM_MBRDY, c & 1);      // both CTAs staged
                uint64_t ahi = make_desc(sb + SM_AHI);
                uint64_t alo = make_desc(sb + SM_ALO);
                uint64_t bh[2] = {make_desc(sb + SM_B0HI), make_desc(sb + SM_B1HI)};
                uint64_t bl[2] = {make_desc(sb + SM_B0LO), make_desc(sb + SM_B1LO)};
#pragma unroll
                for (int p = 0; p < 2; p++) {
                    uint64_t ap[3] = {ahi, ahi, alo};
                    uint64_t bp[3] = {bh[p], bl[p], bh[p]};
                    uint32_t d = tmem + (p << 7);
#pragma unroll
                    for (int pp = 0; pp < 3; pp++) {
#pragma unroll
                        for (int ks = 0; ks < 4; ks++) {
                            uint32_t en = !(c == 0 && pp == 0 && ks == 0);
                            mma_cg2(d, ap[pp] + ks * 2, bp[pp] + ks * 2,
                                    IDESC_CG2, en);
                        }
                    }
                }
                TC_COMMIT_MC2(sb + SM_MBDN);
            }
        }
    }

    MBAR_WAIT(sb + SM_MBDN, (nch - 1) & 1);
    TC_FENCE_AFTER();
    __syncthreads();

    // Epilogue (round-8 proven): this CTA's D = 128 rows x 256 cols.
    int pw = wid >> 2, ws = wid & 3;
    float* sbuf = (float*)smem;   // 128 x 65 floats (stage area reuse)
#pragma unroll
    for (int bt = 0; bt < 4; bt++) {
        uint32_t r[32];
        LDTM_X32(r, tmem + (pw << 7) + bt * 32);
        TC_WAIT_LD();
        int row = ws * 32 + lane;
#pragma unroll
        for (int j = 0; j < 32; j++)
            sbuf[row * 65 + pw * 32 + j] = __uint_as_float(r[j]);
        __syncthreads();
#pragma unroll
        for (int i = 0; i < 8; i++) {
            int idx = tid + i * 256;
            int rw = idx >> 4, c4 = (idx & 15) << 2;
            int gcol = ((c4 >= 32) ? 128 : 0) + bt * 32 + (c4 & 31);
            float4 v = make_float4(sbuf[rw * 65 + c4], sbuf[rw * 65 + c4 + 1],
                                   sbuf[rw * 65 + c4 + 2], sbuf[rw * 65 + c4 + 3]);
            *(float4*)(C + (size_t)rw * ldc + gcol) = v;
        }
        __syncthreads();
    }
    if (wid == 0) TC_DEALLOC_CG2(tmem, 256);
    CLUSTER_SYNC();   // no CTA exits while peer MMA/TMEM traffic in flight

#else  // ----- fp32 SIMT fallback (plain sm_103 PTX pass; never selected) -----
    int tid = threadIdx.x;
    for (int e = tid; e < 128 * 256; e += 256) {
        int i = e >> 8, j = e & 255;
        float acc = 0.0f;
        for (int k = 0; k < kmax; k++)
            acc = fmaf(A[(size_t)(rank * 128 + i) * lda + k],
                       B[(size_t)j * ldb + k], acc);
        C[(size_t)i * ldc + j] = acc;
    }
#endif
}

// ---------------------------------------------------------------------------
// Block reduction (256 threads)
// ---------------------------------------------------------------------------
__device__ __forceinline__ float block_reduce(float v, bool is_max) {
    __shared__ float red[8];
    int lane = threadIdx.x & 31, w = threadIdx.x >> 5;
#pragma unroll
    for (int o = 16; o; o >>= 1) {
        float u = __shfl_xor_sync(0xffffffffu, v, o);
        v = is_max ? fmaxf(v, u) : (v + u);
    }
    if (lane == 0) red[w] = v;
    __syncthreads();
    if (w == 0) {
        float t = (lane < 8) ? red[lane] : (is_max ? -3.4e38f : 0.0f);
#pragma unroll
        for (int o = 4; o; o >>= 1) {
            float u = __shfl_xor_sync(0xffffffffu, t, o);
            t = is_max ? fmaxf(t, u) : (t + u);
        }
        if (lane == 0) red[0] = t;
    }
    __syncthreads();
    float r = red[0];
    __syncthreads();
    return r;
}

// ---------------------------------------------------------------------------
// LayerNorm
// ---------------------------------------------------------------------------
__global__ void ln_kernel(const float* __restrict__ x,
                          const float* __restrict__ gamma,
                          const float* __restrict__ beta) {
    int row = blockIdx.x;
    const float* xr = x + (size_t)row * Dd;
    float* o = g_xn + (size_t)row * Dd;
    int t = threadIdx.x;
    float v0 = xr[t], v1 = xr[t + 256];
    float mu = block_reduce(v0 + v1, false) * (1.0f / Dd);
    float d0 = v0 - mu, d1 = v1 - mu;
    float var = block_reduce(d0 * d0 + d1 * d1, false) * (1.0f / Dd);
    float inv = 1.0f / sqrtf(var + 1e-6f);
    o[t]       = d0 * inv * gamma[t]       + beta[t];
    o[t + 256] = d1 * inv * gamma[t + 256] + beta[t + 256];
}

// ---------------------------------------------------------------------------
// Tiled fp32 transpose: [R][C] -> [C][R], batched over blockIdx.z
// ---------------------------------------------------------------------------
__device__ __forceinline__ void tr_dev(const float* __restrict__ src,
                                       float* __restrict__ dst, int R, int C) {
    __shared__ float t[32][33];
    size_t bo = (size_t)blockIdx.z * R * C;
    int c0 = blockIdx.x * 32, r0 = blockIdx.y * 32;
    int tx = threadIdx.x, ty = threadIdx.y;
#pragma unroll
    for (int i = 0; i < 4; i++)
        t[ty + i * 8][tx] = src[bo + (size_t)(r0 + ty + i * 8) * C + c0 + tx];
    __syncthreads();
#pragma unroll
    for (int i = 0; i < 4; i++)
        dst[bo + (size_t)(c0 + ty + i * 8) * R + r0 + tx] = t[tx][ty + i * 8];
}

__global__ void trw_kernel(const float* __restrict__ src, int wsel) {
    tr_dev(src, g_wt + (size_t)wsel * Hh * Uu * Dd, Dd, Uu);
}
__global__ void trwo_kernel(const float* __restrict__ src) {
    tr_dev(src, g_wot, HU, Dd);
}
__global__ void trv_kernel() {
    tr_dev(g_v, g_vt, Ss, Uu);
}

// ---------------------------------------------------------------------------
// GEMM wrappers: cluster (2,1,1); tile col = blockIdx.x>>1 (256 wide)
// ---------------------------------------------------------------------------
__global__ __launch_bounds__(256, 2) __cluster_dims__(2, 1, 1) void qkv_tc() {
    int z = blockIdx.z;
    int which = z >> 2, h = z & 3;
    const float* Bp = g_wt + (size_t)z * Uu * Dd;
    float* Cb = (which == 0 ? g_q : which == 1 ? g_k : g_v) + (size_t)h * BS * Uu;
    int br = blockIdx.y * 256, bc = (blockIdx.x >> 1) * 256;
    gemm_main(g_xn + (size_t)br * Dd, Dd, Bp + (size_t)bc * Dd, Dd,
              Cb + (size_t)br * Uu + bc, Uu, Dd);
}

__global__ __launch_bounds__(256, 2) __cluster_dims__(2, 1, 1) void scores_tc() {
    int brT = blockIdx.y, bcT = blockIdx.x >> 1;
    if (bcT > brT) return;   // tile fully above causal diagonal
    int br = brT * 256, bc = bcT * 256;
    int z = blockIdx.z, b = z >> 2, h = z & 3;
    const float* Qh = g_q + ((size_t)h * BS + (size_t)b * Ss) * Uu;
    const float* Kh = g_k + ((size_t)h * BS + (size_t)b * Ss) * Uu;
    float* C = g_sc + (size_t)(b * Hh + h) * Ss * Ss;
    gemm_main(Qh + (size_t)br * Uu, Uu, Kh + (size_t)bc * Uu, Uu,
              C + (size_t)br * Ss + bc, Ss, Uu);
}

__global__ __launch_bounds__(256, 2) __cluster_dims__(2, 1, 1) void pv_tc() {
    int z = blockIdx.z, b = z >> 2, h = z & 3;
    int br = blockIdx.y * 256, bc = (blockIdx.x >> 1) * 256;
    const float* P = g_sc + (size_t)(b * Hh + h) * Ss * Ss;
    const float* Vt = g_vt + (size_t)(h * Bb + b) * Uu * Ss;
    float* C = g_cat + (size_t)(b * Ss + br) * HU + h * Uu + bc;
    gemm_main(P + (size_t)br * Ss, Ss, Vt + (size_t)bc * Ss, Ss, C, HU, br + 256);
}

__global__ __launch_bounds__(256, 2) __cluster_dims__(2, 1, 1) void out_tc(float* __restrict__ out) {
    int br = blockIdx.y * 256, bc = (blockIdx.x >> 1) * 256;
    gemm_main(g_cat + (size_t)br * HU, HU, g_wot + (size_t)bc * HU, HU,
              out + (size_t)br * Dd + bc, Dd, HU);
}

// ---------------------------------------------------------------------------
// Softmax (causal, unscaled). Zero-fills (i, 256-block end) for PV.
// ---------------------------------------------------------------------------
__global__ void softmax_kernel() {
    int row = blockIdx.x;
    int i = row & (Ss - 1);
    float* r = g_sc + (size_t)row * Ss;
    int n = i + 1;
    int t = threadIdx.x;

    float v[8];
    float m = -3.4e38f;
#pragma unroll
    for (int c = 0; c < 8; c++) {
        int j = t + c * 256;
        v[c] = (j < n) ? r[j] : -3.4e38f;
        m = fmaxf(m, v[c]);
    }
    m = block_reduce(m, true);
    float s = 0.0f;
#pragma unroll
    for (int c = 0; c < 8; c++) {
        v[c] = expf(v[c] - m);
        s += v[c];
    }
    s = block_reduce(s, false);
    float inv = 1.0f / s;
#pragma unroll
    for (int c = 0; c < 8; c++) {
        int j = t + c * 256;
        if (j < n) r[j] = v[c] * inv;
    }
    int end = ((i >> 8) + 1) << 8;   // 256-aligned (PV tile k-extent)
    for (int j = n + t; j < end; j += 256) r[j] = 0.0f;
}

// ---------------------------------------------------------------------------
extern "C" void kernel_launch(void* const* d_in, const int* in_sizes, int n_in,
                              void* d_out, int out_size) {
    const float* x     = (const float*)d_in[0];
    const float* gamma = (const float*)d_in[1];
    const float* beta  = (const float*)d_in[2];
    const float* Wq    = (const float*)d_in[3];
    const float* Wk    = (const float*)d_in[4];
    const float* Wv    = (const float*)d_in[5];
    const float* Wout  = (const float*)d_in[6];
    float* out = (float*)d_out;

    cudaFuncSetAttribute(qkv_tc,    cudaFuncAttributeMaxDynamicSharedMemorySize, SMEM_BYTES);
    cudaFuncSetAttribute(scores_tc, cudaFuncAttributeMaxDynamicSharedMemorySize, SMEM_BYTES);
    cudaFuncSetAttribute(pv_tc,     cudaFuncAttributeMaxDynamicSharedMemorySize, SMEM_BYTES);
    cudaFuncSetAttribute(out_tc,    cudaFuncAttributeMaxDynamicSharedMemorySize, SMEM_BYTES);

    dim3 tb(32, 8);

    ln_kernel<<<BS, 256>>>(x, gamma, beta);
    trw_kernel<<<dim3(Uu / 32, Dd / 32, Hh), tb>>>(Wq, 0);
    trw_kernel<<<dim3(Uu / 32, Dd / 32, Hh), tb>>>(Wk, 1);
    trw_kernel<<<dim3(Uu / 32, Dd / 32, Hh), tb>>>(Wv, 2);
    trwo_kernel<<<dim3(Dd / 32, HU / 32, 1), tb>>>(Wout);

    qkv_tc<<<dim3((Uu / 256) * 2, BS / 256, 12), 256, SMEM_BYTES>>>();
    trv_kernel<<<dim3(Uu / 32, Ss / 32, Bb * Hh), tb>>>();
    scores_tc<<<dim3((Ss / 256) * 2, Ss / 256, Bb * Hh), 256, SMEM_BYTES>>>();
    softmax_kernel<<<Bb * Hh * Ss, 256>>>();
    pv_tc<<<dim3((Uu / 256) * 2, Ss / 256, Bb * Hh), 256, SMEM_BYTES>>>();
    out_tc<<<dim3((Dd / 256) * 2, BS / 256), 256, SMEM_BYTES>>>(out);
}

// round 16
// speedup vs baseline: 1.4270x; 1.2738x over previous
#include <cuda_runtime.h>
#include <cuda_bf16.h>
#include <cstdint>
#include <math.h>

// Problem constants
#define Bb 4
#define Hh 4
#define Ss 2048
#define Dd 512
#define Uu 1024
#define BS 8192          // Bb*Ss
#define HU 4096          // Hh*Uu

// Arch feature gate: tcgen05 only exists on the 'a' variants.
#if defined(__CUDA_ARCH_FEAT_SM103_ALL) || defined(__CUDA_ARCH_FEAT_SM100_ALL)
#define HAS_TCGEN05 1
#else
#define HAS_TCGEN05 0
#endif

// ---------------------------------------------------------------------------
// Device scratch (no cudaMalloc allowed)
// ---------------------------------------------------------------------------
__device__ float g_xn[BS * Dd];                       // 16 MB
__device__ float g_q[(size_t)Hh * BS * Uu];           // 134 MB
__device__ float g_k[(size_t)Hh * BS * Uu];           // 134 MB
__device__ float g_v[(size_t)Hh * BS * Uu];           // 134 MB
__device__ float g_vt[(size_t)Hh * BS * Uu];          // 134 MB (V^T [h][b][u][t])
__device__ float g_sc[(size_t)Bb * Hh * Ss * Ss];     // 268 MB
__device__ float g_cat[(size_t)BS * HU];              // 134 MB
__device__ float g_wt[(size_t)3 * Hh * Uu * Dd];      // 25 MB  (W^T for q,k,v)
__device__ float g_wot[(size_t)Dd * HU];              // 8 MB   (Wout^T [512][4096])

// ---------------------------------------------------------------------------
// helpers
// ---------------------------------------------------------------------------
__device__ __forceinline__ uint32_t smem_u32(const void* p) {
    uint32_t a;
    asm("{ .reg .u64 t; cvta.to.shared.u64 t, %1; cvt.u32.u64 %0, t; }" : "=r"(a) : "l"(p));
    return a;
}
__device__ __forceinline__ uint32_t cluster_rank() {
    uint32_t r;
    asm("mov.u32 %0, %%cluster_ctarank;" : "=r"(r));
    return r;
}

#if HAS_TCGEN05
__device__ __forceinline__ uint32_t elect_one() {
    uint32_t pred;
    asm volatile("{\n\t.reg .pred p;\n\telect.sync _|p, 0xFFFFFFFF;\n\t"
                 "selp.b32 %0, 1, 0, p;\n\t}" : "=r"(pred));
    return pred;
}
#define MBAR_INIT(addr, cnt) \
    asm volatile("mbarrier.init.shared.b64 [%0], %1;" :: "r"(addr), "r"(cnt) : "memory")
#define MBAR_WAIT(addr, parity) do {                                              \
    uint32_t _m = (addr), _p = (parity), _d;                                      \
    asm volatile("{\n\t.reg .pred p;\n\t"                                         \
        "mbarrier.try_wait.parity.acquire.cta.shared::cta.b64 p, [%1], %2;\n\t"   \
        "selp.b32 %0, 1, 0, p;\n\t}" : "=r"(_d) : "r"(_m), "r"(_p) : "memory");   \
    if (!_d) {                                                                    \
        asm volatile("{\n\t.reg .pred P1;\n\t"                                    \
            "W_%=:\n\t"                                                           \
            "mbarrier.try_wait.parity.acquire.cta.shared::cta.b64 P1, [%0], %1, 0x989680;\n\t" \
            "@P1 bra.uni D_%=;\n\t"                                               \
            "bra.uni W_%=;\n\t"                                                   \
            "D_%=:\n\t}" :: "r"(_m), "r"(_p) : "memory");                         \
    }                                                                             \
} while (0)
// cluster-scope acquire wait (pairs with peer CTA's cluster arrive)
#define MBAR_WAIT_CLU(addr, parity) do {                                          \
    uint32_t _m = (addr), _p = (parity), _d;                                      \
    asm volatile("{\n\t.reg .pred p;\n\t"                                         \
        "mbarrier.try_wait.parity.acquire.cluster.shared::cta.b64 p, [%1], %2;\n\t" \
        "selp.b32 %0, 1, 0, p;\n\t}" : "=r"(_d) : "r"(_m), "r"(_p) : "memory");   \
    if (!_d) {                                                                    \
        asm volatile("{\n\t.reg .pred P1;\n\t"                                    \
            "W_%=:\n\t"                                                           \
            "mbarrier.try_wait.parity.acquire.cluster.shared::cta.b64 P1, [%0], %1, 0x989680;\n\t" \
            "@P1 bra.uni D_%=;\n\t"                                               \
            "bra.uni W_%=;\n\t"                                                   \
            "D_%=:\n\t}" :: "r"(_m), "r"(_p) : "memory");                         \
    }                                                                             \
} while (0)
// arrive at rank0's copy of the given smem mbar (ptx_helpers-proven form)
#define MBAR_ARRIVE_RANK0(addr) \
    asm volatile("{\n\t.reg .b32 ra;\n\t" \
        "mapa.shared::cluster.u32 ra, %0, 0;\n\t" \
        "mbarrier.arrive.shared::cluster.b64 _, [ra];\n\t}" \
        :: "r"(addr) : "memory")
#define TC_ALLOC_CG2(smem_addr, n) \
    asm volatile("tcgen05.alloc.cta_group::2.sync.aligned.shared::cta.b32 [%0], %1;" \
                 :: "r"(smem_addr), "r"((uint32_t)(n)) : "memory")
#define TC_DEALLOC_CG2(tmem, n) \
    asm volatile("tcgen05.dealloc.cta_group::2.sync.aligned.b32 %0, %1;" :: "r"(tmem), "r"((uint32_t)(n)))
#define TC_COMMIT_MC2(mbar) \
    asm volatile("tcgen05.commit.cta_group::2.mbarrier::arrive::one.shared::cluster.multicast::cluster.b64 [%0], %1;" \
                 :: "r"(mbar), "h"((uint16_t)3) : "memory")
#define TC_FENCE_AFTER()  asm volatile("tcgen05.fence::after_thread_sync;" ::: "memory")
#define TC_WAIT_LD()      asm volatile("tcgen05.wait::ld.sync.aligned;" ::: "memory")
#define FENCE_ASYNC()     asm volatile("fence.proxy.async.shared::cta;" ::: "memory")
#define CLUSTER_SYNC() do { \
    asm volatile("barrier.cluster.arrive.aligned;" ::: "memory"); \
    asm volatile("barrier.cluster.wait.aligned;" ::: "memory"); \
} while (0)

#define LDTM_X32(r, addr)                                                         \
    asm volatile("tcgen05.ld.sync.aligned.32x32b.x32.b32 "                        \
        "{%0, %1, %2, %3, %4, %5, %6, %7, %8, %9, %10, %11, %12, %13, %14, %15, " \
        " %16, %17, %18, %19, %20, %21, %22, %23, %24, %25, %26, %27, %28, %29, %30, %31}, [%32];" \
        : "=r"((r)[0]), "=r"((r)[1]), "=r"((r)[2]), "=r"((r)[3]),                 \
          "=r"((r)[4]), "=r"((r)[5]), "=r"((r)[6]), "=r"((r)[7]),                 \
          "=r"((r)[8]), "=r"((r)[9]), "=r"((r)[10]), "=r"((r)[11]),               \
          "=r"((r)[12]), "=r"((r)[13]), "=r"((r)[14]), "=r"((r)[15]),             \
          "=r"((r)[16]), "=r"((r)[17]), "=r"((r)[18]), "=r"((r)[19]),             \
          "=r"((r)[20]), "=r"((r)[21]), "=r"((r)[22]), "=r"((r)[23]),             \
          "=r"((r)[24]), "=r"((r)[25]), "=r"((r)[26]), "=r"((r)[27]),             \
          "=r"((r)[28]), "=r"((r)[29]), "=r"((r)[30]), "=r"((r)[31])              \
        : "r"(addr))

__device__ __forceinline__ void sts64(uint32_t addr, uint32_t a, uint32_t b) {
    asm volatile("st.shared.v2.b32 [%0], {%1,%2};"
                 :: "r"(addr), "r"(a), "r"(b) : "memory");
}

// pack two f32 into bf16x2 (low = x) with a single cvt
__device__ __forceinline__ uint32_t packbf2(float x, float y) {
    uint32_t r;
    asm("cvt.rn.bf16x2.f32 %0, %1, %2;" : "=r"(r) : "f"(y), "f"(x));
    return r;
}

// SMEM descriptor, SW128, LBO=1 (16B), SBO=64 (1024B)
__device__ __forceinline__ uint64_t make_desc(uint32_t addr) {
    const uint64_t base = (2ULL << 61) | (1ULL << 46) | (64ULL << 32) | (1ULL << 16);
    return base | (uint64_t)((addr >> 4) & 0x3FFF);
}
// cg2 f16(bf16) SS MMA: M=256 across the pair
__device__ __forceinline__ void mma_cg2(uint32_t d, uint64_t ad, uint64_t bd,
                                        uint32_t idesc, uint32_t en) {
    asm volatile("{\n\t.reg .pred p;\n\tsetp.ne.u32 p, %4, 0;\n\t"
        "tcgen05.mma.cta_group::2.kind::f16 [%0], %1, %2, %3, "
        "{%5,%5,%5,%5,%5,%5,%5,%5}, p;\n\t}"
        :: "r"(d), "l"(ad), "l"(bd), "r"(idesc), "r"(en), "r"(0u) : "memory");
}
#endif  // HAS_TCGEN05

// idesc: fp32 accum, bf16 A/B, M=256 (cg2), N=128 (round-8/11 proven)
#define IDESC_CG2 0x10200490u

// SMEM per CTA: TWO stages x (A half 128x64 hi/lo + two B panels 64x64 hi/lo)
#define STG 65536
#define SM_AHI(s)  ((s) * STG + 0)
#define SM_ALO(s)  ((s) * STG + 16384)
#define SM_B0HI(s) ((s) * STG + 32768)
#define SM_B0LO(s) ((s) * STG + 40960)
#define SM_B1HI(s) ((s) * STG + 49152)
#define SM_B1LO(s) ((s) * STG + 57344)
#define SM_MBDN(s)  (131072 + (s) * 8)
#define SM_MBRDY(s) (131088 + (s) * 8)
#define SM_TPTR 131104
#define SMEM_BYTES 131136

#if HAS_TCGEN05
// ---------------------------------------------------------------------------
// Two-phase stage (round-7/8/11 proven): fp32 K-major tile -> hi/lo bf16 SW128.
// 16 threads/row contiguous LDG.128; rows staged = ITERS * 16.
// ---------------------------------------------------------------------------
template <int ITERS>
__device__ __forceinline__ void stage(const float* __restrict__ src, int ld,
                                      uint32_t hi, uint32_t lo, int tid) {
    float4 v[ITERS];
#pragma unroll
    for (int i = 0; i < ITERS; i++) {
        int idx = tid + i * 256;
        int r = idx >> 4, q = idx & 15;
        v[i] = *(const float4*)(src + (size_t)r * ld + (q << 2));
    }
#pragma unroll
    for (int i = 0; i < ITERS; i++) {
        int idx = tid + i * 256;
        int r = idx >> 4, q = idx & 15;
        uint32_t h0 = packbf2(v[i].x, v[i].y);
        uint32_t h1 = packbf2(v[i].z, v[i].w);
        uint32_t l0 = packbf2(v[i].x - __uint_as_float(h0 << 16),
                              v[i].y - __uint_as_float(h0 & 0xFFFF0000u));
        uint32_t l1 = packbf2(v[i].z - __uint_as_float(h1 << 16),
                              v[i].w - __uint_as_float(h1 & 0xFFFF0000u));
        uint32_t b0 = (uint32_t)(r * 128 + (q << 3));
        uint32_t o = b0 ^ ((b0 >> 3) & 0x70);
        sts64(hi + o, h0, h1);
        sts64(lo + o, l0, l1);
    }
}
#endif

// ---------------------------------------------------------------------------
// Main GEMM (cg2 pair, double-buffered): C[256 x 256] = A[256 x k] * B[256 x k]^T
// Rank r stages A rows [r*128,+128) and B rows [p*128+r*64,+64) per panel p.
// Stage c -> buffer c&1; MMA of chunk c overlaps staging of chunk c+1.
// Sync per chunk: ready mbar (2 arrivals -> rank0, cluster scope) + multicast
// done mbar. Phase bookkeeping = round-3 proven ph[s]++-after-wait scheme.
// ---------------------------------------------------------------------------
__device__ void gemm_main(const float* __restrict__ A, int lda,
                          const float* __restrict__ B, int ldb,
                          float* __restrict__ C, int ldc, int kmax) {
    uint32_t rank = cluster_rank();
    C += (size_t)(rank * 128) * ldc;           // this CTA's M half
#if HAS_TCGEN05
    extern __shared__ char smem[];
    uint32_t sb = smem_u32(smem);
    int tid = threadIdx.x;
    int wid = tid >> 5;
    int lane = tid & 31;

    if (wid == 0) TC_ALLOC_CG2(sb + SM_TPTR, 256);
    if (tid == 0) {
        MBAR_INIT(sb + SM_MBDN(0), 1);  MBAR_INIT(sb + SM_MBDN(1), 1);
        MBAR_INIT(sb + SM_MBRDY(0), 2); MBAR_INIT(sb + SM_MBRDY(1), 2);
    }
    __syncthreads();
    uint32_t tmem = *(volatile uint32_t*)(smem + SM_TPTR);
    CLUSTER_SYNC();   // mbars + alloc visible cluster-wide

    int nch = kmax >> 6;
    int dnph[2] = {0, 0};   // done phases (stager side)
    int rdph[2] = {0, 0};   // ready phases (MMA-issuer side; used by elected lane)

    for (int c = 0; c < nch; c++) {
        int s = c & 1;
        if (c >= 2) { MBAR_WAIT(sb + SM_MBDN(s), dnph[s] & 1); dnph[s]++; }
        stage<8>(A + (size_t)(rank * 128) * lda + c * 64, lda,
                 sb + SM_AHI(s), sb + SM_ALO(s), tid);
        stage<4>(B + (size_t)(rank * 64) * ldb + c * 64, ldb,
                 sb + SM_B0HI(s), sb + SM_B0LO(s), tid);
        stage<4>(B + (size_t)(128 + rank * 64) * ldb + c * 64, ldb,
                 sb + SM_B1HI(s), sb + SM_B1LO(s), tid);
        FENCE_ASYNC();
        __syncthreads();
        if (tid == 0) MBAR_ARRIVE_RANK0(sb + SM_MBRDY(s));   // both ranks -> rank0
        if (rank == 0 && wid == 0) {
            if (elect_one()) {
                MBAR_WAIT_CLU(sb + SM_MBRDY(s), rdph[s] & 1);  // both CTAs staged s
                rdph[s]++;
                uint64_t ahi = make_desc(sb + SM_AHI(s));
                uint64_t alo = make_desc(sb + SM_ALO(s));
                uint64_t bh[2] = {make_desc(sb + SM_B0HI(s)), make_desc(sb + SM_B1HI(s))};
                uint64_t bl[2] = {make_desc(sb + SM_B0LO(s)), make_desc(sb + SM_B1LO(s))};
#pragma unroll
                for (int p = 0; p < 2; p++) {
                    uint64_t ap[3] = {ahi, ahi, alo};
                    uint64_t bp[3] = {bh[p], bl[p], bh[p]};
                    uint32_t d = tmem + (p << 7);
#pragma unroll
                    for (int pp = 0; pp < 3; pp++) {
#pragma unroll
                        for (int ks = 0; ks < 4; ks++) {
                            uint32_t en = !(c == 0 && pp == 0 && ks == 0);
                            mma_cg2(d, ap[pp] + ks * 2, bp[pp] + ks * 2,
                                    IDESC_CG2, en);
                        }
                    }
                }
                TC_COMMIT_MC2(sb + SM_MBDN(s));
            }
        }
    }

    // Drain both stages (round-3 proven pattern)
    if (nch > 0) MBAR_WAIT(sb + SM_MBDN(0), dnph[0] & 1);
    if (nch > 1) MBAR_WAIT(sb + SM_MBDN(1), dnph[1] & 1);
    TC_FENCE_AFTER();
    __syncthreads();

    // Epilogue (round-8/11 proven): this CTA's D = 128 rows x 256 cols.
    int pw = wid >> 2, ws = wid & 3;
    float* sbuf = (float*)smem;   // 128 x 65 floats (stage area reuse)
#pragma unroll
    for (int bt = 0; bt < 4; bt++) {
        uint32_t r[32];
        LDTM_X32(r, tmem + (pw << 7) + bt * 32);
        TC_WAIT_LD();
        int row = ws * 32 + lane;
#pragma unroll
        for (int j = 0; j < 32; j++)
            sbuf[row * 65 + pw * 32 + j] = __uint_as_float(r[j]);
        __syncthreads();
#pragma unroll
        for (int i = 0; i < 8; i++) {
            int idx = tid + i * 256;
            int rw = idx >> 4, c4 = (idx & 15) << 2;
            int gcol = ((c4 >= 32) ? 128 : 0) + bt * 32 + (c4 & 31);
            float4 v = make_float4(sbuf[rw * 65 + c4], sbuf[rw * 65 + c4 + 1],
                                   sbuf[rw * 65 + c4 + 2], sbuf[rw * 65 + c4 + 3]);
            *(float4*)(C + (size_t)rw * ldc + gcol) = v;
        }
        __syncthreads();
    }
    if (wid == 0) TC_DEALLOC_CG2(tmem, 256);
    CLUSTER_SYNC();   // no CTA exits while peer MMA/TMEM traffic in flight

#else  // ----- fp32 SIMT fallback (plain sm_103 PTX pass; never selected) -----
    int tid = threadIdx.x;
    for (int e = tid; e < 128 * 256; e += 256) {
        int i = e >> 8, j = e & 255;
        float acc = 0.0f;
        for (int k = 0; k < kmax; k++)
            acc = fmaf(A[(size_t)(rank * 128 + i) * lda + k],
                       B[(size_t)j * ldb + k], acc);
        C[(size_t)i * ldc + j] = acc;
    }
#endif
}

// ---------------------------------------------------------------------------
// Block reduction (256 threads)
// ---------------------------------------------------------------------------
__device__ __forceinline__ float block_reduce(float v, bool is_max) {
    __shared__ float red[8];
    int lane = threadIdx.x & 31, w = threadIdx.x >> 5;
#pragma unroll
    for (int o = 16; o; o >>= 1) {
        float u = __shfl_xor_sync(0xffffffffu, v, o);
        v = is_max ? fmaxf(v, u) : (v + u);
    }
    if (lane == 0) red[w] = v;
    __syncthreads();
    if (w == 0) {
        float t = (lane < 8) ? red[lane] : (is_max ? -3.4e38f : 0.0f);
#pragma unroll
        for (int o = 4; o; o >>= 1) {
            float u = __shfl_xor_sync(0xffffffffu, t, o);
            t = is_max ? fmaxf(t, u) : (t + u);
        }
        if (lane == 0) red[0] = t;
    }
    __syncthreads();
    float r = red[0];
    __syncthreads();
    return r;
}

// ---------------------------------------------------------------------------
// LayerNorm
// ---------------------------------------------------------------------------
__global__ void ln_kernel(const float* __restrict__ x,
                          const float* __restrict__ gamma,
                          const float* __restrict__ beta) {
    int row = blockIdx.x;
    const float* xr = x + (size_t)row * Dd;
    float* o = g_xn + (size_t)row * Dd;
    int t = threadIdx.x;
    float v0 = xr[t], v1 = xr[t + 256];
    float mu = block_reduce(v0 + v1, false) * (1.0f / Dd);
    float d0 = v0 - mu, d1 = v1 - mu;
    float var = block_reduce(d0 * d0 + d1 * d1, false) * (1.0f / Dd);
    float inv = 1.0f / sqrtf(var + 1e-6f);
    o[t]       = d0 * inv * gamma[t]       + beta[t];
    o[t + 256] = d1 * inv * gamma[t + 256] + beta[t + 256];
}

// ---------------------------------------------------------------------------
// Tiled fp32 transpose: [R][C] -> [C][R], batched over blockIdx.z
// ---------------------------------------------------------------------------
__device__ __forceinline__ void tr_dev(const float* __restrict__ src,
                                       float* __restrict__ dst, int R, int C) {
    __shared__ float t[32][33];
    size_t bo = (size_t)blockIdx.z * R * C;
    int c0 = blockIdx.x * 32, r0 = blockIdx.y * 32;
    int tx = threadIdx.x, ty = threadIdx.y;
#pragma unroll
    for (int i = 0; i < 4; i++)
        t[ty + i * 8][tx] = src[bo + (size_t)(r0 + ty + i * 8) * C + c0 + tx];
    __syncthreads();
#pragma unroll
    for (int i = 0; i < 4; i++)
        dst[bo + (size_t)(c0 + ty + i * 8) * R + r0 + tx] = t[tx][ty + i * 8];
}

__global__ void trw_kernel(const float* __restrict__ src, int wsel) {
    tr_dev(src, g_wt + (size_t)wsel * Hh * Uu * Dd, Dd, Uu);
}
__global__ void trwo_kernel(const float* __restrict__ src) {
    tr_dev(src, g_wot, HU, Dd);
}
__global__ void trv_kernel() {
    tr_dev(g_v, g_vt, Ss, Uu);
}

// ---------------------------------------------------------------------------
// GEMM wrappers: cluster (2,1,1); tile col = blockIdx.x>>1 (256 wide)
// ---------------------------------------------------------------------------
__global__ __launch_bounds__(256, 1) __cluster_dims__(2, 1, 1) void qkv_tc() {
    int z = blockIdx.z;
    int which = z >> 2, h = z & 3;
    const float* Bp = g_wt + (size_t)z * Uu * Dd;
    float* Cb = (which == 0 ? g_q : which == 1 ? g_k : g_v) + (size_t)h * BS * Uu;
    int br = blockIdx.y * 256, bc = (blockIdx.x >> 1) * 256;
    gemm_main(g_xn + (size_t)br * Dd, Dd, Bp + (size_t)bc * Dd, Dd,
              Cb + (size_t)br * Uu + bc, Uu, Dd);
}

__global__ __launch_bounds__(256, 1) __cluster_dims__(2, 1, 1) void scores_tc() {
    int brT = blockIdx.y, bcT = blockIdx.x >> 1;
    if (bcT > brT) return;   // tile fully above causal diagonal
    int br = brT * 256, bc = bcT * 256;
    int z = blockIdx.z, b = z >> 2, h = z & 3;
    const float* Qh = g_q + ((size_t)h * BS + (size_t)b * Ss) * Uu;
    const float* Kh = g_k + ((size_t)h * BS + (size_t)b * Ss) * Uu;
    float* C = g_sc + (size_t)(b * Hh + h) * Ss * Ss;
    gemm_main(Qh + (size_t)br * Uu, Uu, Kh + (size_t)bc * Uu, Uu,
              C + (size_t)br * Ss + bc, Ss, Uu);
}

__global__ __launch_bounds__(256, 1) __cluster_dims__(2, 1, 1) void pv_tc() {
    int z = blockIdx.z, b = z >> 2, h = z & 3;
    int br = blockIdx.y * 256, bc = (blockIdx.x >> 1) * 256;
    const float* P = g_sc + (size_t)(b * Hh + h) * Ss * Ss;
    const float* Vt = g_vt + (size_t)(h * Bb + b) * Uu * Ss;
    float* C = g_cat + (size_t)(b * Ss + br) * HU + h * Uu + bc;
    gemm_main(P + (size_t)br * Ss, Ss, Vt + (size_t)bc * Ss, Ss, C, HU, br + 256);
}

__global__ __launch_bounds__(256, 1) __cluster_dims__(2, 1, 1) void out_tc(float* __restrict__ out) {
    int br = blockIdx.y * 256, bc = (blockIdx.x >> 1) * 256;
    gemm_main(g_cat + (size_t)br * HU, HU, g_wot + (size_t)bc * HU, HU,
              out + (size_t)br * Dd + bc, Dd, HU);
}

// ---------------------------------------------------------------------------
// Softmax (causal, unscaled). Zero-fills (i, 256-block end) for PV.
// ---------------------------------------------------------------------------
__global__ void softmax_kernel() {
    int row = blockIdx.x;
    int i = row & (Ss - 1);
    float* r = g_sc + (size_t)row * Ss;
    int n = i + 1;
    int t = threadIdx.x;

    float v[8];
    float m = -3.4e38f;
#pragma unroll
    for (int c = 0; c < 8; c++) {
        int j = t + c * 256;
        v[c] = (j < n) ? r[j] : -3.4e38f;
        m = fmaxf(m, v[c]);
    }
    m = block_reduce(m, true);
    float s = 0.0f;
#pragma unroll
    for (int c = 0; c < 8; c++) {
        v[c] = expf(v[c] - m);
        s += v[c];
    }
    s = block_reduce(s, false);
    float inv = 1.0f / s;
#pragma unroll
    for (int c = 0; c < 8; c++) {
        int j = t + c * 256;
        if (j < n) r[j] = v[c] * inv;
    }
    int end = ((i >> 8) + 1) << 8;   // 256-aligned (PV tile k-extent)
    for (int j = n + t; j < end; j += 256) r[j] = 0.0f;
}

// ---------------------------------------------------------------------------
extern "C" void kernel_launch(void* const* d_in, const int* in_sizes, int n_in,
                              void* d_out, int out_size) {
    const float* x     = (const float*)d_in[0];
    const float* gamma = (const float*)d_in[1];
    const float* beta  = (const float*)d_in[2];
    const float* Wq    = (const float*)d_in[3];
    const float* Wk    = (const float*)d_in[4];
    const float* Wv    = (const float*)d_in[5];
    const float* Wout  = (const float*)d_in[6];
    float* out = (float*)d_out;

    cudaFuncSetAttribute(qkv_tc,    cudaFuncAttributeMaxDynamicSharedMemorySize, SMEM_BYTES);
    cudaFuncSetAttribute(scores_tc, cudaFuncAttributeMaxDynamicSharedMemorySize, SMEM_BYTES);
    cudaFuncSetAttribute(pv_tc,     cudaFuncAttributeMaxDynamicSharedMemorySize, SMEM_BYTES);
    cudaFuncSetAttribute(out_tc,    cudaFuncAttributeMaxDynamicSharedMemorySize, SMEM_BYTES);

    dim3 tb(32, 8);

    ln_kernel<<<BS, 256>>>(x, gamma, beta);
    trw_kernel<<<dim3(Uu / 32, Dd / 32, Hh), tb>>>(Wq, 0);
    trw_kernel<<<dim3(Uu / 32, Dd / 32, Hh), tb>>>(Wk, 1);
    trw_kernel<<<dim3(Uu / 32, Dd / 32, Hh), tb>>>(Wv, 2);
    trwo_kernel<<<dim3(Dd / 32, HU / 32, 1), tb>>>(Wout);

    qkv_tc<<<dim3((Uu / 256) * 2, BS / 256, 12), 256, SMEM_BYTES>>>();
    trv_kernel<<<dim3(Uu / 32, Ss / 32, Bb * Hh), tb>>>();
    scores_tc<<<dim3((Ss / 256) * 2, Ss / 256, Bb * Hh), 256, SMEM_BYTES>>>();
    softmax_kernel<<<Bb * Hh * Ss, 256>>>();
    pv_tc<<<dim3((Uu / 256) * 2, Ss / 256, Bb * Hh), 256, SMEM_BYTES>>>();
    out_tc<<<dim3((Dd / 256) * 2, BS / 256), 256, SMEM_BYTES>>>(out);
}